// round 15
// baseline (speedup 1.0000x reference)
#include <cuda_runtime.h>
#include <math.h>

// Problem constants (fixed by the reference)
#define BB 8
#define NN 900
#define CC 256
#define HEADS 8
#define PP 4
#define HD 32
#define BH 200
#define BW 200
#define HW (BH*BW)
#define RADIUS 0.2f
#define QB 8                  // queries per block
#define NBLK ((BB*NN)/QB)     // 900 blocks; all resident in one wave at cap 7
#define TST 12                // bufT row stride (floats): 48B, 16B-aligned

__device__ __forceinline__ unsigned long long pk2(float x) {
    unsigned long long r;
    asm("mov.b64 %0, {%1, %1};" : "=l"(r) : "f"(x));
    return r;
}
__device__ __forceinline__ void ffma2(unsigned long long& acc,
                                      unsigned long long a,
                                      unsigned long long b) {
    asm("fma.rn.f32x2 %0, %1, %2, %0;" : "+l"(acc) : "l"(a), "l"(b));
}
__device__ __forceinline__ void unpk2(unsigned long long v, float& lo, float& hi) {
    asm("mov.b64 {%0, %1}, %2;" : "=f"(lo), "=f"(hi) : "l"(v));
}

// cap 7 blocks/SM: 148*7=1036 >= 900 -> single wave, 73-register budget
__global__ __launch_bounds__(128, 7)
void deform_fused_kernel(
    const float* __restrict__ query,
    const float* __restrict__ memory,
    const float* __restrict__ refpts,
    const float* __restrict__ w_off,
    const float* __restrict__ b_off,
    const float* __restrict__ w_wt,
    const float* __restrict__ b_wt,
    const float* __restrict__ w_out,
    const float* __restrict__ b_out,
    float* __restrict__ out)
{
    // Transposed union buffer: phases 1-2 hold queryT[k][q]; phases 4-5 hold fusedT[k][q]
    __shared__ float bufT[CC][TST];              // 12 KB
    __shared__ float ow_s[96][9];                // 3.4 KB (odd stride -> conflict-free reads)
    __shared__ float ref_s[QB][2];
    __shared__ float sampw_s[QB][HEADS*PP][4];   // 4 KB (rows 16B-aligned)
    __shared__ int   sampi_s[QB][HEADS*PP][4];   // 4 KB

    const int t = threadIdx.x;
    const int base = blockIdx.x * QB;

    // Early prefetch of phase-2 W (independent of bufT; overlaps phase-1 barrier)
    const bool gemv = (t < 96);
    const bool is_off = (t < 64);
    const float* Wg = is_off ? w_off : w_wt;
    const int colg = is_off ? t : (t - 64);
    const int ldwg = is_off ? 64 : 32;
    float wc[4];
    if (gemv) {
        #pragma unroll
        for (int j = 0; j < 4; j++) wc[j] = Wg[j*ldwg + colg];
    } else if (t < 96 + 2*QB) {
        const int qq = (t - 96) >> 1, c = (t - 96) & 1;
        ref_s[qq][c] = refpts[(size_t)(base + qq)*2 + c];
    }

    // ---- Phase 1: stage QB query rows, transposed ----
    #pragma unroll
    for (int half = 0; half < 2; half++) {
        const int k = t + half*128;
        #pragma unroll
        for (int j = 0; j < QB; j++)
            bufT[k][j] = query[(size_t)(base + j)*CC + k];
    }
    __syncthreads();

    // ---- Phase 2: offset+weight GEMV (threads 0..95) ----
    if (gemv) {
        unsigned long long acc[4];
        #pragma unroll
        for (int u = 0; u < 4; u++) acc[u] = 0ull;

        float wn[4];
        #pragma unroll 1
        for (int kb = 0; kb < CC; kb += 4) {
            const bool more = (kb + 4) < CC;
            #pragma unroll
            for (int j = 0; j < 4; j++)
                wn[j] = more ? Wg[(kb + 4 + j)*ldwg + colg] : 0.f;
            #pragma unroll
            for (int j = 0; j < 4; j++) {
                const unsigned long long ww = pk2(wc[j]);
                ulonglong2 r0 = *(const ulonglong2*)&bufT[kb + j][0];  // q0..3
                ulonglong2 r1 = *(const ulonglong2*)&bufT[kb + j][4];  // q4..7
                ffma2(acc[0], r0.x, ww);
                ffma2(acc[1], r0.y, ww);
                ffma2(acc[2], r1.x, ww);
                ffma2(acc[3], r1.y, ww);
            }
            #pragma unroll
            for (int j = 0; j < 4; j++) wc[j] = wn[j];
        }
        #pragma unroll
        for (int u = 0; u < 4; u++) {
            float lo, hi; unpk2(acc[u], lo, hi);
            ow_s[t][2*u+0] = lo;
            ow_s[t][2*u+1] = hi;
        }
    }
    __syncthreads();

    // ---- Phase 3: bias, tanh, softmax(P), bilinear setup ----
    {
        const int lane = t & 31;
        #pragma unroll
        for (int rep = 0; rep < 2; rep++) {
            const int qq = (t >> 5) + rep*4;
            float rx = ref_s[qq][0];
            float ry = ref_s[qq][1];

            float lgx = ow_s[2*lane  ][qq] + b_off[2*lane  ];
            float lgy = ow_s[2*lane+1][qq] + b_off[2*lane+1];
            float ox = tanhf(lgx) * RADIUS;
            float oy = tanhf(lgy) * RADIUS;
            float x = (rx + ox) * (float)BW - 0.5f;
            float y = (ry + oy) * (float)BH - 0.5f;
            float x0f = floorf(x), y0f = floorf(y);
            int   x0 = (int)x0f,   y0 = (int)y0f;
            float fx = x - x0f,    fy = y - y0f;

            float lg = ow_s[64 + lane][qq] + b_wt[lane];
            float m = lg;
            m = fmaxf(m, __shfl_xor_sync(0xffffffffu, m, 1));
            m = fmaxf(m, __shfl_xor_sync(0xffffffffu, m, 2));
            float e = expf(lg - m);
            float s = e;
            s += __shfl_xor_sync(0xffffffffu, s, 1);
            s += __shfl_xor_sync(0xffffffffu, s, 2);
            float wt = e / s;

            #pragma unroll
            for (int c = 0; c < 4; c++) {
                int xi = x0 + (c & 1);
                int yi = y0 + (c >> 1);
                bool valid = (xi >= 0) & (xi < BW) & (yi >= 0) & (yi < BH);
                float bwx = (c & 1)  ? fx : (1.f - fx);
                float bwy = (c >> 1) ? fy : (1.f - fy);
                int xc = min(max(xi, 0), BW - 1);
                int yc = min(max(yi, 0), BH - 1);
                sampw_s[qq][lane][c] = valid ? (wt * bwx * bwy) : 0.f;
                sampi_s[qq][lane][c] = yc * BW + xc;
            }
        }
    }
    __syncthreads();

    // ---- Phase 4: software-pipelined gather (next iter's 16 LDGs in flight
    //      while consuming current) ; warp = 2 heads; write transposed ----
    {
        const int w = t >> 5, d = t & 31;

        // issue: launch 16 gather LDGs for iteration `it` into vbuf
        auto issue = [&](int it, float* vbuf) {
            const int qq = it >> 1, h = 2*w + (it & 1);
            const float* mb = memory
                + (size_t)((base + qq) / NN) * (size_t)(HW*CC) + h*HD + d;
            #pragma unroll
            for (int u = 0; u < 4; u++) {
                int4 iv = *(const int4*)&sampi_s[qq][h*4 + u][0];   // warp-uniform
                vbuf[4*u+0] = mb[(size_t)iv.x * CC];
                vbuf[4*u+1] = mb[(size_t)iv.y * CC];
                vbuf[4*u+2] = mb[(size_t)iv.z * CC];
                vbuf[4*u+3] = mb[(size_t)iv.w * CC];
            }
        };
        // consume: weighted sum of vbuf for iteration `it`, store to bufT
        auto consume = [&](int it, const float* vbuf) {
            const int qq = it >> 1, h = 2*w + (it & 1);
            float a0 = 0.f, a1 = 0.f;
            #pragma unroll
            for (int u = 0; u < 4; u++) {
                float4 wv = *(const float4*)&sampw_s[qq][h*4 + u][0]; // warp-uniform
                a0 += wv.x * vbuf[4*u+0];
                a1 += wv.y * vbuf[4*u+1];
                a0 += wv.z * vbuf[4*u+2];
                a1 += wv.w * vbuf[4*u+3];
            }
            bufT[h*HD + d][qq] = a0 + a1;
        };

        float vA[16], vB[16];
        issue(0, vA);
        #pragma unroll 1
        for (int i = 0; i < 2*QB; i += 2) {
            issue(i + 1, vB);
            consume(i, vA);
            if (i + 2 < 2*QB) issue(i + 2, vA);
            consume(i + 1, vB);
        }
    }

    // Early prefetch of phase-5 w_out (independent of bufT; overlaps barrier)
    float wc0[4], wc1[4];
    #pragma unroll
    for (int j = 0; j < 4; j++) {
        wc0[j] = w_out[(size_t)j*CC + t];
        wc1[j] = w_out[(size_t)j*CC + t + 128];
    }
    __syncthreads();

    // ---- Phase 5: output projection; thread handles cols t and t+128 ----
    {
        unsigned long long acc[8];
        #pragma unroll
        for (int u = 0; u < 8; u++) acc[u] = 0ull;

        float wn0[4], wn1[4];
        #pragma unroll 1
        for (int kb = 0; kb < CC; kb += 4) {
            const bool more = (kb + 4) < CC;
            #pragma unroll
            for (int j = 0; j < 4; j++) {
                wn0[j] = more ? w_out[(size_t)(kb + 4 + j)*CC + t]       : 0.f;
                wn1[j] = more ? w_out[(size_t)(kb + 4 + j)*CC + t + 128] : 0.f;
            }
            #pragma unroll
            for (int j = 0; j < 4; j++) {
                const int k = kb + j;
                ulonglong2 r0 = *(const ulonglong2*)&bufT[k][0];  // q0..3
                ulonglong2 r1 = *(const ulonglong2*)&bufT[k][4];  // q4..7
                const unsigned long long w0 = pk2(wc0[j]);
                const unsigned long long w1 = pk2(wc1[j]);
                ffma2(acc[0], r0.x, w0);
                ffma2(acc[1], r0.y, w0);
                ffma2(acc[2], r1.x, w0);
                ffma2(acc[3], r1.y, w0);
                ffma2(acc[4], r0.x, w1);
                ffma2(acc[5], r0.y, w1);
                ffma2(acc[6], r1.x, w1);
                ffma2(acc[7], r1.y, w1);
            }
            #pragma unroll
            for (int j = 0; j < 4; j++) { wc0[j] = wn0[j]; wc1[j] = wn1[j]; }
        }

        const float bo0 = b_out[t];
        const float bo1 = b_out[t + 128];
        #pragma unroll
        for (int u = 0; u < 4; u++) {
            float lo, hi;
            unpk2(acc[u], lo, hi);
            out[(size_t)(base + 2*u + 0)*CC + t] = lo + bo0;
            out[(size_t)(base + 2*u + 1)*CC + t] = hi + bo0;
            unpk2(acc[4+u], lo, hi);
            out[(size_t)(base + 2*u + 0)*CC + t + 128] = lo + bo1;
            out[(size_t)(base + 2*u + 1)*CC + t + 128] = hi + bo1;
        }
    }
}

extern "C" void kernel_launch(void* const* d_in, const int* in_sizes, int n_in,
                              void* d_out, int out_size) {
    const float* query  = (const float*)d_in[0];
    const float* memory = (const float*)d_in[1];
    const float* refpts = (const float*)d_in[2];
    const float* w_off  = (const float*)d_in[3];
    const float* b_off  = (const float*)d_in[4];
    const float* w_wt   = (const float*)d_in[5];
    const float* b_wt   = (const float*)d_in[6];
    const float* w_out  = (const float*)d_in[7];
    const float* b_out  = (const float*)d_in[8];

    deform_fused_kernel<<<NBLK, 128>>>(query, memory, refpts,
                                       w_off, b_off, w_wt, b_wt,
                                       w_out, b_out, (float*)d_out);
}

// round 16
// speedup vs baseline: 1.1465x; 1.1465x over previous
#include <cuda_runtime.h>
#include <math.h>

// Problem constants (fixed by the reference)
#define BB 8
#define NN 900
#define CC 256
#define HEADS 8
#define PP 4
#define HD 32
#define BH 200
#define BW 200
#define HW (BH*BW)
#define RADIUS 0.2f
#define QB 8                  // queries per block
#define NBLK ((BB*NN)/QB)     // 900 blocks; all resident in one wave at cap 7
#define TST 12                // bufT row stride (floats): 48B, 16B-aligned

__device__ __forceinline__ unsigned long long pk2(float x) {
    unsigned long long r;
    asm("mov.b64 %0, {%1, %1};" : "=l"(r) : "f"(x));
    return r;
}
__device__ __forceinline__ void ffma2(unsigned long long& acc,
                                      unsigned long long a,
                                      unsigned long long b) {
    asm("fma.rn.f32x2 %0, %1, %2, %0;" : "+l"(acc) : "l"(a), "l"(b));
}
__device__ __forceinline__ void unpk2(unsigned long long v, float& lo, float& hi) {
    asm("mov.b64 {%0, %1}, %2;" : "=f"(lo), "=f"(hi) : "l"(v));
}

// cap 7 blocks/SM: 148*7=1036 >= 900 -> single wave, 73-register budget
__global__ __launch_bounds__(128, 7)
void deform_fused_kernel(
    const float* __restrict__ query,
    const float* __restrict__ memory,
    const float* __restrict__ refpts,
    const float* __restrict__ w_off,
    const float* __restrict__ b_off,
    const float* __restrict__ w_wt,
    const float* __restrict__ b_wt,
    const float* __restrict__ w_out,
    const float* __restrict__ b_out,
    float* __restrict__ out)
{
    // Transposed union buffer: phases 1-2 hold queryT[k][q]; phases 4-5 hold fusedT[k][q]
    __shared__ float bufT[CC][TST];              // 12 KB
    __shared__ float ow_s[96][9];                // 3.4 KB (odd stride -> conflict-free reads)
    __shared__ float ref_s[QB][2];
    __shared__ float sampw_s[QB][HEADS*PP][4];   // 4 KB (rows 16B-aligned)
    __shared__ int   sampi_s[QB][HEADS*PP][4];   // 4 KB

    const int t = threadIdx.x;
    const int base = blockIdx.x * QB;

    // Early prefetch of phase-2 W (independent of bufT; overlaps phase-1 barrier)
    const bool gemv = (t < 96);
    const bool is_off = (t < 64);
    const float* Wg = is_off ? w_off : w_wt;
    const int colg = is_off ? t : (t - 64);
    const int ldwg = is_off ? 64 : 32;
    float wc[4];
    if (gemv) {
        #pragma unroll
        for (int j = 0; j < 4; j++) wc[j] = Wg[j*ldwg + colg];
    } else if (t < 96 + 2*QB) {
        const int qq = (t - 96) >> 1, c = (t - 96) & 1;
        ref_s[qq][c] = refpts[(size_t)(base + qq)*2 + c];
    }

    // ---- Phase 1: stage QB query rows, transposed (streaming loads) ----
    #pragma unroll
    for (int half = 0; half < 2; half++) {
        const int k = t + half*128;
        #pragma unroll
        for (int j = 0; j < QB; j++)
            bufT[k][j] = __ldcs(&query[(size_t)(base + j)*CC + k]);
    }
    __syncthreads();

    // ---- Phase 2: offset+weight GEMV (threads 0..95) ----
    if (gemv) {
        unsigned long long acc[4];
        #pragma unroll
        for (int u = 0; u < 4; u++) acc[u] = 0ull;

        float wn[4];
        #pragma unroll 1
        for (int kb = 0; kb < CC; kb += 4) {
            const bool more = (kb + 4) < CC;
            #pragma unroll
            for (int j = 0; j < 4; j++)
                wn[j] = more ? Wg[(kb + 4 + j)*ldwg + colg] : 0.f;
            #pragma unroll
            for (int j = 0; j < 4; j++) {
                const unsigned long long ww = pk2(wc[j]);
                ulonglong2 r0 = *(const ulonglong2*)&bufT[kb + j][0];  // q0..3
                ulonglong2 r1 = *(const ulonglong2*)&bufT[kb + j][4];  // q4..7
                ffma2(acc[0], r0.x, ww);
                ffma2(acc[1], r0.y, ww);
                ffma2(acc[2], r1.x, ww);
                ffma2(acc[3], r1.y, ww);
            }
            #pragma unroll
            for (int j = 0; j < 4; j++) wc[j] = wn[j];
        }
        #pragma unroll
        for (int u = 0; u < 4; u++) {
            float lo, hi; unpk2(acc[u], lo, hi);
            ow_s[t][2*u+0] = lo;
            ow_s[t][2*u+1] = hi;
        }
    }
    __syncthreads();

    // ---- Phase 3: bias, tanh, softmax(P), bilinear setup ----
    {
        const int lane = t & 31;
        #pragma unroll
        for (int rep = 0; rep < 2; rep++) {
            const int qq = (t >> 5) + rep*4;
            float rx = ref_s[qq][0];
            float ry = ref_s[qq][1];

            float lgx = ow_s[2*lane  ][qq] + b_off[2*lane  ];
            float lgy = ow_s[2*lane+1][qq] + b_off[2*lane+1];
            float ox = tanhf(lgx) * RADIUS;
            float oy = tanhf(lgy) * RADIUS;
            float x = (rx + ox) * (float)BW - 0.5f;
            float y = (ry + oy) * (float)BH - 0.5f;
            float x0f = floorf(x), y0f = floorf(y);
            int   x0 = (int)x0f,   y0 = (int)y0f;
            float fx = x - x0f,    fy = y - y0f;

            float lg = ow_s[64 + lane][qq] + b_wt[lane];
            float m = lg;
            m = fmaxf(m, __shfl_xor_sync(0xffffffffu, m, 1));
            m = fmaxf(m, __shfl_xor_sync(0xffffffffu, m, 2));
            float e = expf(lg - m);
            float s = e;
            s += __shfl_xor_sync(0xffffffffu, s, 1);
            s += __shfl_xor_sync(0xffffffffu, s, 2);
            float wt = e / s;

            #pragma unroll
            for (int c = 0; c < 4; c++) {
                int xi = x0 + (c & 1);
                int yi = y0 + (c >> 1);
                bool valid = (xi >= 0) & (xi < BW) & (yi >= 0) & (yi < BH);
                float bwx = (c & 1)  ? fx : (1.f - fx);
                float bwy = (c >> 1) ? fy : (1.f - fy);
                int xc = min(max(xi, 0), BW - 1);
                int yc = min(max(yi, 0), BH - 1);
                sampw_s[qq][lane][c] = valid ? (wt * bwx * bwy) : 0.f;
                sampi_s[qq][lane][c] = yc * BW + xc;
            }
        }
    }
    __syncthreads();

    // ---- Phase 4: gather with streaming loads (no L1 allocate);
    //      warp = 2 heads; write transposed ----
    {
        const int w = t >> 5, d = t & 31;
        #pragma unroll 1
        for (int qq = 0; qq < QB; qq++) {
            const float* mbase = memory + (size_t)((base + qq) / NN) * (size_t)(HW*CC);
            #pragma unroll
            for (int hh = 0; hh < 2; hh++) {
                const int h = 2*w + hh;
                const float* mb = mbase + h*HD + d;

                float4 wv[4]; int4 iv[4];
                #pragma unroll
                for (int u = 0; u < 4; u++) {
                    wv[u] = *(const float4*)&sampw_s[qq][h*4 + u][0];   // warp-uniform
                    iv[u] = *(const int4*)&sampi_s[qq][h*4 + u][0];     // warp-uniform
                }
                float v[16];
                #pragma unroll
                for (int u = 0; u < 4; u++) {
                    v[4*u+0] = __ldcs(&mb[(size_t)iv[u].x * CC]);
                    v[4*u+1] = __ldcs(&mb[(size_t)iv[u].y * CC]);
                    v[4*u+2] = __ldcs(&mb[(size_t)iv[u].z * CC]);
                    v[4*u+3] = __ldcs(&mb[(size_t)iv[u].w * CC]);
                }
                float a0 = 0.f, a1 = 0.f;
                #pragma unroll
                for (int u = 0; u < 4; u++) {
                    a0 += wv[u].x * v[4*u+0];
                    a1 += wv[u].y * v[4*u+1];
                    a0 += wv[u].z * v[4*u+2];
                    a1 += wv[u].w * v[4*u+3];
                }
                bufT[h*HD + d][qq] = a0 + a1;   // fusedT[k][q]
            }
        }
    }

    // ---- Phase 5 setup: thread owns 4 consecutive cols x 4 queries ----
    const int cg = (t & 63) * 4;    // column group base (0,4,...,252)
    const int qh = (t >> 6) * 4;    // query half base (0 or 4)

    // Early prefetch of first w_out tile (independent of bufT; overlaps barrier)
    float4 wc4[4];
    #pragma unroll
    for (int j = 0; j < 4; j++)
        wc4[j] = *(const float4*)&w_out[(size_t)j*CC + cg];
    __syncthreads();

    // ---- Phase 5: output projection, vectorized (LDG.128 + LDS.128) ----
    {
        // acc[c][p]: column cg+c, query pair (qh+2p, qh+2p+1)
        unsigned long long acc[4][2];
        #pragma unroll
        for (int c = 0; c < 4; c++) { acc[c][0] = 0ull; acc[c][1] = 0ull; }

        float4 wn4[4];
        #pragma unroll 1
        for (int kb = 0; kb < CC; kb += 4) {
            const bool more = (kb + 4) < CC;
            #pragma unroll
            for (int j = 0; j < 4; j++)
                wn4[j] = more ? *(const float4*)&w_out[(size_t)(kb + 4 + j)*CC + cg]
                              : make_float4(0.f, 0.f, 0.f, 0.f);
            #pragma unroll
            for (int j = 0; j < 4; j++) {
                const int k = kb + j;
                // 4-query packed pair: LDS.128, warp-uniform broadcast
                ulonglong2 fp = *(const ulonglong2*)&bufT[k][qh];
                const unsigned long long w0 = pk2(wc4[j].x);
                const unsigned long long w1 = pk2(wc4[j].y);
                const unsigned long long w2 = pk2(wc4[j].z);
                const unsigned long long w3 = pk2(wc4[j].w);
                ffma2(acc[0][0], fp.x, w0); ffma2(acc[0][1], fp.y, w0);
                ffma2(acc[1][0], fp.x, w1); ffma2(acc[1][1], fp.y, w1);
                ffma2(acc[2][0], fp.x, w2); ffma2(acc[2][1], fp.y, w2);
                ffma2(acc[3][0], fp.x, w3); ffma2(acc[3][1], fp.y, w3);
            }
            #pragma unroll
            for (int j = 0; j < 4; j++) wc4[j] = wn4[j];
        }

        const float4 bo = *(const float4*)&b_out[cg];
        #pragma unroll
        for (int p = 0; p < 2; p++) {
            float lo0, hi0, lo1, hi1, lo2, hi2, lo3, hi3;
            unpk2(acc[0][p], lo0, hi0);
            unpk2(acc[1][p], lo1, hi1);
            unpk2(acc[2][p], lo2, hi2);
            unpk2(acc[3][p], lo3, hi3);
            float4 o0 = make_float4(lo0 + bo.x, lo1 + bo.y, lo2 + bo.z, lo3 + bo.w);
            float4 o1 = make_float4(hi0 + bo.x, hi1 + bo.y, hi2 + bo.z, hi3 + bo.w);
            __stcs((float4*)&out[(size_t)(base + qh + 2*p + 0)*CC + cg], o0);
            __stcs((float4*)&out[(size_t)(base + qh + 2*p + 1)*CC + cg], o1);
        }
    }
}

extern "C" void kernel_launch(void* const* d_in, const int* in_sizes, int n_in,
                              void* d_out, int out_size) {
    const float* query  = (const float*)d_in[0];
    const float* memory = (const float*)d_in[1];
    const float* refpts = (const float*)d_in[2];
    const float* w_off  = (const float*)d_in[3];
    const float* b_off  = (const float*)d_in[4];
    const float* w_wt   = (const float*)d_in[5];
    const float* b_wt   = (const float*)d_in[6];
    const float* w_out  = (const float*)d_in[7];
    const float* b_out  = (const float*)d_in[8];

    deform_fused_kernel<<<NBLK, 128>>>(query, memory, refpts,
                                       w_off, b_off, w_wt, b_wt,
                                       w_out, b_out, (float*)d_out);
}